// round 4
// baseline (speedup 1.0000x reference)
#include <cuda_runtime.h>
#include <cstdint>

// Problem constants
#define NB    4
#define NN    262144
#define NBUCK 1024
#define KSEL  6000
#define CAP   8192
#define PROP  1000
#define NMS_THR 0.7f

// ---------------- device scratch (no allocations allowed) ----------------
__device__ int                g_hist[NB][NBUCK];
__device__ int                g_cnt[NB];
__device__ int                g_bstar[NB];
__device__ unsigned long long g_keys[NB][CAP];
__device__ int                g_topidx[NB][KSEL];
__device__ float4             g_boxes[NB][KSEL];

// ---------------- kernel Z: zero scratch ----------------
__global__ void k_zero() {
    int t = blockIdx.x * blockDim.x + threadIdx.x;
    int total = NB * NBUCK;
    for (int p = t; p < total; p += gridDim.x * blockDim.x)
        ((int*)g_hist)[p] = 0;
    if (t < NB) g_cnt[t] = 0;
}

// ---------------- kernel A: per-batch histogram of fg scores ----------------
// grid (64, NB) x 256 threads; each block handles 4096 elements
__global__ void k_hist(const float2* __restrict__ scores) {
    __shared__ int sh[NBUCK];
    int t = threadIdx.x;
    int b = blockIdx.y;
    for (int p = t; p < NBUCK; p += 256) sh[p] = 0;
    __syncthreads();
    int base = blockIdx.x * 4096;
    const float2* sp = scores + (size_t)b * NN;
    #pragma unroll
    for (int r = 0; r < 16; ++r) {
        float s = sp[base + r * 256 + t].y;        // fg score
        int bk = (int)(s * 1024.0f);
        if (bk > NBUCK - 1) bk = NBUCK - 1;
        if (bk < 0) bk = 0;
        atomicAdd(&sh[bk], 1);
    }
    __syncthreads();
    for (int p = t; p < NBUCK; p += 256)
        if (sh[p]) atomicAdd(&g_hist[b][p], sh[p]);
}

// ---------------- kernel B: suffix-sum scan, find threshold bucket ----------------
// grid NB x 1024 threads
__global__ void k_findthr() {
    __shared__ int s[NBUCK];
    int b = blockIdx.x, t = threadIdx.x;
    s[t] = g_hist[b][t];
    __syncthreads();
    // inclusive suffix sum (Hillis-Steele)
    for (int off = 1; off < NBUCK; off <<= 1) {
        int v = (t + off < NBUCK) ? s[t + off] : 0;
        __syncthreads();
        s[t] += v;
        __syncthreads();
    }
    // b* = largest t with suffix[t] >= KSEL
    if (s[t] >= KSEL && (t == NBUCK - 1 || s[t + 1] < KSEL))
        g_bstar[b] = t;
}

// ---------------- kernel C: compact candidates >= threshold bucket ----------------
__global__ void k_compact(const float2* __restrict__ scores) {
    int t = threadIdx.x;
    int b = blockIdx.y;
    int bstar = g_bstar[b];
    int base = blockIdx.x * 4096;
    const float2* sp = scores + (size_t)b * NN;
    #pragma unroll
    for (int r = 0; r < 16; ++r) {
        int i = base + r * 256 + t;
        float s = sp[i].y;
        int bk = (int)(s * 1024.0f);
        if (bk > NBUCK - 1) bk = NBUCK - 1;
        if (bk >= bstar) {
            int pos = atomicAdd(&g_cnt[b], 1);
            if (pos < CAP) {
                unsigned sb = __float_as_uint(s);   // s >= 0 -> monotonic bits
                g_keys[b][pos] =
                    ((unsigned long long)sb << 32) | (0xFFFFFFFFu - (unsigned)i);
            }
        }
    }
}

// ---------------- kernel D: bitonic sort (desc) of up to 8192 keys ----------------
// grid NB x 1024 threads, 64KB dynamic shared
__global__ void k_sort() {
    extern __shared__ unsigned long long sk[];
    int b = blockIdx.x, t = threadIdx.x;
    int n = g_cnt[b];
    if (n > CAP) n = CAP;
    for (int p = t; p < CAP; p += 1024)
        sk[p] = (p < n) ? g_keys[b][p] : 0ULL;
    __syncthreads();
    for (int k = 2; k <= CAP; k <<= 1) {
        for (int j = k >> 1; j > 0; j >>= 1) {
            for (int i = t; i < CAP; i += 1024) {
                int ixj = i ^ j;
                if (ixj > i) {
                    unsigned long long a = sk[i], c = sk[ixj];
                    bool desc = ((i & k) == 0);
                    if (desc ? (a < c) : (a > c)) { sk[i] = c; sk[ixj] = a; }
                }
            }
            __syncthreads();
        }
    }
    for (int r = t; r < KSEL; r += 1024)
        g_topidx[b][r] = (int)(0xFFFFFFFFu - (unsigned)(sk[r] & 0xFFFFFFFFull));
}

// ---------------- kernel E: gather + apply box deltas + clip ----------------
__global__ void k_boxes(const float4* __restrict__ deltas,
                        const float4* __restrict__ anchors) {
    int gid = blockIdx.x * blockDim.x + threadIdx.x;
    if (gid >= NB * KSEL) return;
    int b = gid / KSEL;
    int r = gid - b * KSEL;
    int j = g_topidx[b][r];
    float4 a = anchors[(size_t)b * NN + j];
    float4 d = deltas[(size_t)b * NN + j];
    float dx = d.x * 0.1f, dy = d.y * 0.1f, dw = d.z * 0.2f, dh = d.w * 0.2f;
    float w  = a.z - a.x;
    float h  = a.w - a.y;
    float cx = a.x + 0.5f * w;
    float cy = a.y + 0.5f * h;
    cx = cx + dx * w;
    cy = cy + dy * h;
    w  = w * expf(dw);
    h  = h * expf(dh);
    float x0 = cx - 0.5f * w, y0 = cy - 0.5f * h;
    float x1 = cx + 0.5f * w, y1 = cy + 0.5f * h;
    x0 = fminf(fmaxf(x0, 0.0f), 1.0f);
    y0 = fminf(fmaxf(y0, 0.0f), 1.0f);
    x1 = fminf(fmaxf(x1, 0.0f), 1.0f);
    y1 = fminf(fmaxf(y1, 0.0f), 1.0f);
    g_boxes[b][r] = make_float4(x0, y0, x1, y1);
}

// ---------------- kernel G: greedy NMS with early exit at PROP kept ----------------
// grid NB x 128 threads
__global__ void k_nms(float* __restrict__ out) {
    __shared__ float4 skept[PROP];
    __shared__ float  skarea[PROP];
    __shared__ int    sm_m;
    int b = blockIdx.x, t = threadIdx.x;
    float* outB = out + (size_t)b * PROP * 4;
    // pre-zero output (harness poisons it)
    for (int p = t; p < PROP * 4; p += 128) outB[p] = 0.0f;
    if (t == 0) sm_m = 0;
    __syncthreads();

    const float4* boxes = g_boxes[b];
    for (int i = 0; i < KSEL; ++i) {
        int m = sm_m;
        if (m >= PROP) break;
        float4 box = boxes[i];                       // broadcast load
        float ai = __fmul_rn(box.z - box.x, box.w - box.y);
        int pred = 0;
        for (int p = t; p < m; p += 128) {
            float4 kb = skept[p];
            float  ka = skarea[p];
            float ltx = fmaxf(box.x, kb.x);
            float lty = fmaxf(box.y, kb.y);
            float rbx = fminf(box.z, kb.z);
            float rby = fminf(box.w, kb.w);
            float wx = fmaxf(rbx - ltx, 0.0f);
            float wy = fmaxf(rby - lty, 0.0f);
            float inter = __fmul_rn(wx, wy);
            // exact reference order: ((a_i + a_j) - inter) + 1e-12
            float denom = ((ai + ka) - inter) + 1e-12f;
            float iou = __fdiv_rn(inter, denom);
            pred |= (iou > NMS_THR);
        }
        int any = __syncthreads_or(pred);
        if (!any) {
            if (t == 0) {
                skept[m]  = box;
                skarea[m] = ai;
                sm_m = m + 1;
                ((float4*)outB)[m] = box;
            }
        }
        __syncthreads();
    }
}

// ---------------- launch ----------------
extern "C" void kernel_launch(void* const* d_in, const int* in_sizes, int n_in,
                              void* d_out, int out_size) {
    const float2* scores  = (const float2*)d_in[0];  // (4,262144,2)
    const float4* deltas  = (const float4*)d_in[1];  // (4,262144,4)
    const float4* anchors = (const float4*)d_in[2];  // (4,262144,4)
    float* out = (float*)d_out;                      // (4,1000,4)

    cudaFuncSetAttribute(k_sort, cudaFuncAttributeMaxDynamicSharedMemorySize,
                         CAP * sizeof(unsigned long long));

    k_zero<<<8, 512>>>();
    k_hist<<<dim3(64, NB), 256>>>(scores);
    k_findthr<<<NB, NBUCK>>>();
    k_compact<<<dim3(64, NB), 256>>>(scores);
    k_sort<<<NB, 1024, CAP * sizeof(unsigned long long)>>>();
    k_boxes<<<(NB * KSEL + 255) / 256, 256>>>(deltas, anchors);
    k_nms<<<NB, 128>>>(out);
}

// round 7
// speedup vs baseline: 1.5468x; 1.5468x over previous
#include <cuda_runtime.h>
#include <cstdint>

// Problem constants
#define NB    4
#define NN    262144
#define NBUCK 1024
#define KSEL  6000
#define CAP   8192
#define PROP  1000
#define NMS_THR 0.7f

// dynamic smem layout for k_nms: sboxes | skept | skarea
#define NMS_SMEM_BYTES (KSEL * 16 + PROP * 16 + PROP * 4)

// ---------------- device scratch (no allocations allowed) ----------------
__device__ int                g_hist[NB][NBUCK];
__device__ int                g_cnt[NB];
__device__ int                g_bstar[NB];
__device__ unsigned long long g_keys[NB][CAP];
__device__ int                g_topidx[NB][KSEL];
__device__ float4             g_boxes[NB][KSEL];

// ---------------- kernel Z: zero scratch ----------------
__global__ void k_zero() {
    int t = blockIdx.x * blockDim.x + threadIdx.x;
    int total = NB * NBUCK;
    for (int p = t; p < total; p += gridDim.x * blockDim.x)
        ((int*)g_hist)[p] = 0;
    if (t < NB) g_cnt[t] = 0;
}

// ---------------- kernel A: per-batch histogram of fg scores ----------------
__global__ void k_hist(const float2* __restrict__ scores) {
    __shared__ int sh[NBUCK];
    int t = threadIdx.x;
    int b = blockIdx.y;
    for (int p = t; p < NBUCK; p += 256) sh[p] = 0;
    __syncthreads();
    int base = blockIdx.x * 4096;
    const float2* sp = scores + (size_t)b * NN;
    #pragma unroll
    for (int r = 0; r < 16; ++r) {
        float s = sp[base + r * 256 + t].y;        // fg score
        int bk = (int)(s * 1024.0f);
        if (bk > NBUCK - 1) bk = NBUCK - 1;
        if (bk < 0) bk = 0;
        atomicAdd(&sh[bk], 1);
    }
    __syncthreads();
    for (int p = t; p < NBUCK; p += 256)
        if (sh[p]) atomicAdd(&g_hist[b][p], sh[p]);
}

// ---------------- kernel B: suffix-sum scan, find threshold bucket ----------------
__global__ void k_findthr() {
    __shared__ int s[NBUCK];
    int b = blockIdx.x, t = threadIdx.x;
    s[t] = g_hist[b][t];
    __syncthreads();
    for (int off = 1; off < NBUCK; off <<= 1) {
        int v = (t + off < NBUCK) ? s[t + off] : 0;
        __syncthreads();
        s[t] += v;
        __syncthreads();
    }
    if (s[t] >= KSEL && (t == NBUCK - 1 || s[t + 1] < KSEL))
        g_bstar[b] = t;
}

// ---------------- kernel C: compact candidates >= threshold bucket ----------------
__global__ void k_compact(const float2* __restrict__ scores) {
    int t = threadIdx.x;
    int b = blockIdx.y;
    int bstar = g_bstar[b];
    int base = blockIdx.x * 4096;
    const float2* sp = scores + (size_t)b * NN;
    #pragma unroll
    for (int r = 0; r < 16; ++r) {
        int i = base + r * 256 + t;
        float s = sp[i].y;
        int bk = (int)(s * 1024.0f);
        if (bk > NBUCK - 1) bk = NBUCK - 1;
        if (bk >= bstar) {
            int pos = atomicAdd(&g_cnt[b], 1);
            if (pos < CAP) {
                unsigned sb = __float_as_uint(s);   // s >= 0 -> monotonic bits
                g_keys[b][pos] =
                    ((unsigned long long)sb << 32) | (0xFFFFFFFFu - (unsigned)i);
            }
        }
    }
}

// ---------------- kernel D: bitonic sort (desc) of up to 8192 keys ----------------
__global__ void k_sort() {
    extern __shared__ unsigned long long sk[];
    int b = blockIdx.x, t = threadIdx.x;
    int n = g_cnt[b];
    if (n > CAP) n = CAP;
    for (int p = t; p < CAP; p += 1024)
        sk[p] = (p < n) ? g_keys[b][p] : 0ULL;
    __syncthreads();
    for (int k = 2; k <= CAP; k <<= 1) {
        for (int j = k >> 1; j > 0; j >>= 1) {
            for (int i = t; i < CAP; i += 1024) {
                int ixj = i ^ j;
                if (ixj > i) {
                    unsigned long long a = sk[i], c = sk[ixj];
                    bool desc = ((i & k) == 0);
                    if (desc ? (a < c) : (a > c)) { sk[i] = c; sk[ixj] = a; }
                }
            }
            __syncthreads();
        }
    }
    for (int r = t; r < KSEL; r += 1024)
        g_topidx[b][r] = (int)(0xFFFFFFFFu - (unsigned)(sk[r] & 0xFFFFFFFFull));
}

// ---------------- kernel E: gather + apply box deltas + clip ----------------
__global__ void k_boxes(const float4* __restrict__ deltas,
                        const float4* __restrict__ anchors) {
    int gid = blockIdx.x * blockDim.x + threadIdx.x;
    if (gid >= NB * KSEL) return;
    int b = gid / KSEL;
    int r = gid - b * KSEL;
    int j = g_topidx[b][r];
    float4 a = anchors[(size_t)b * NN + j];
    float4 d = deltas[(size_t)b * NN + j];
    float dx = d.x * 0.1f, dy = d.y * 0.1f, dw = d.z * 0.2f, dh = d.w * 0.2f;
    float w  = a.z - a.x;
    float h  = a.w - a.y;
    float cx = a.x + 0.5f * w;
    float cy = a.y + 0.5f * h;
    cx = cx + dx * w;
    cy = cy + dy * h;
    w  = w * expf(dw);
    h  = h * expf(dh);
    float x0 = cx - 0.5f * w, y0 = cy - 0.5f * h;
    float x1 = cx + 0.5f * w, y1 = cy + 0.5f * h;
    x0 = fminf(fmaxf(x0, 0.0f), 1.0f);
    y0 = fminf(fmaxf(y0, 0.0f), 1.0f);
    x1 = fminf(fmaxf(x1, 0.0f), 1.0f);
    y1 = fminf(fmaxf(y1, 0.0f), 1.0f);
    g_boxes[b][r] = make_float4(x0, y0, x1, y1);
}

// ---------------- kernel G: greedy NMS, smem-staged, single barrier/iter ----------
// grid NB x 256 threads, NMS_SMEM_BYTES dynamic shared
__global__ void __launch_bounds__(256, 1) k_nms(float* __restrict__ out) {
    extern __shared__ unsigned char smem_raw[];
    float4* sboxes = (float4*)smem_raw;                              // KSEL
    float4* skept  = (float4*)(smem_raw + (size_t)KSEL * 16);        // PROP
    float*  skarea = (float*)(smem_raw + (size_t)KSEL * 16 + (size_t)PROP * 16);

    int b = blockIdx.x, t = threadIdx.x;
    float* outB = out + (size_t)b * PROP * 4;
    // pre-zero output (harness poisons it)
    for (int p = t; p < PROP * 4; p += 256) outB[p] = 0.0f;
    // stage all candidate boxes into shared memory (coalesced)
    const float4* gB = g_boxes[b];
    for (int p = t; p < KSEL; p += 256) sboxes[p] = gB[p];
    __syncthreads();

    int m = 0;                       // kept count, tracked uniformly in registers
    float4 box = sboxes[0];
    for (int i = 0; i < KSEL; ++i) {
        // prefetch next candidate (independent of this iteration's outcome)
        float4 nbox = (i + 1 < KSEL) ? sboxes[i + 1] : box;
        float ai = __fmul_rn(box.z - box.x, box.w - box.y);
        int pred = 0;
        for (int p = t; p < m; p += 256) {
            float4 kb = skept[p];
            float  ka = skarea[p];
            float ltx = fmaxf(box.x, kb.x);
            float lty = fmaxf(box.y, kb.y);
            float rbx = fminf(box.z, kb.z);
            float rby = fminf(box.w, kb.w);
            float wx = fmaxf(rbx - ltx, 0.0f);
            float wy = fmaxf(rby - lty, 0.0f);
            float inter = __fmul_rn(wx, wy);
            // exact reference order: ((a_i + a_j) - inter) + 1e-12
            float denom = ((ai + ka) - inter) + 1e-12f;
            float iou = __fdiv_rn(inter, denom);
            pred |= (iou > NMS_THR);
        }
        int any = __syncthreads_or(pred);
        if (!any) {
            // benign same-value race: every thread writes identical bits, and
            // each thread re-reads its OWN write in later iterations.
            skept[m]  = box;
            skarea[m] = ai;
            if (t == 0) ((float4*)outB)[m] = box;
            ++m;
            if (m >= PROP) break;
        }
        box = nbox;
    }
}

// ---------------- launch ----------------
extern "C" void kernel_launch(void* const* d_in, const int* in_sizes, int n_in,
                              void* d_out, int out_size) {
    const float2* scores  = (const float2*)d_in[0];  // (4,262144,2)
    const float4* deltas  = (const float4*)d_in[1];  // (4,262144,4)
    const float4* anchors = (const float4*)d_in[2];  // (4,262144,4)
    float* out = (float*)d_out;                      // (4,1000,4)

    cudaFuncSetAttribute(k_sort, cudaFuncAttributeMaxDynamicSharedMemorySize,
                         CAP * sizeof(unsigned long long));
    cudaFuncSetAttribute(k_nms, cudaFuncAttributeMaxDynamicSharedMemorySize,
                         NMS_SMEM_BYTES);

    k_zero<<<8, 512>>>();
    k_hist<<<dim3(64, NB), 256>>>(scores);
    k_findthr<<<NB, NBUCK>>>();
    k_compact<<<dim3(64, NB), 256>>>(scores);
    k_sort<<<NB, 1024, CAP * sizeof(unsigned long long)>>>();
    k_boxes<<<(NB * KSEL + 255) / 256, 256>>>(deltas, anchors);
    k_nms<<<NB, 256, NMS_SMEM_BYTES>>>(out);
}

// round 12
// speedup vs baseline: 2.8242x; 1.8258x over previous
#include <cuda_runtime.h>
#include <cstdint>

// Problem constants
#define NB    4
#define NN    262144
#define NBUCK 1024
#define KSEL  6000
#define CAP   8192
#define PROP  1000
#define NMS_THR 0.7f
#define MROW64 96          // u64 words per mask row (6144 bits >= 6000)

// ---------------- device scratch (no allocations allowed) ----------------
__device__ int                g_hist[NB][NBUCK];
__device__ int                g_cnt[NB];
__device__ int                g_bstar[NB];
__device__ unsigned long long g_keys[NB][CAP];
__device__ int                g_topidx[NB][KSEL];
__device__ float4             g_boxes[NB][KSEL];
__device__ unsigned long long g_mask[NB][KSEL][MROW64];   // ~18.4 MB

// ---------------- kernel Z: zero scratch ----------------
__global__ void k_zero() {
    int t = blockIdx.x * blockDim.x + threadIdx.x;
    int total = NB * NBUCK;
    for (int p = t; p < total; p += gridDim.x * blockDim.x)
        ((int*)g_hist)[p] = 0;
    if (t < NB) g_cnt[t] = 0;
}

// ---------------- kernel A: per-batch histogram of fg scores ----------------
// grid (256, NB) x 256 threads; each block handles 1024 elements
__global__ void k_hist(const float2* __restrict__ scores) {
    __shared__ int sh[NBUCK];
    int t = threadIdx.x;
    int b = blockIdx.y;
    for (int p = t; p < NBUCK; p += 256) sh[p] = 0;
    __syncthreads();
    int base = blockIdx.x * 1024;
    const float2* sp = scores + (size_t)b * NN;
    #pragma unroll
    for (int r = 0; r < 4; ++r) {
        float s = sp[base + r * 256 + t].y;        // fg score
        int bk = (int)(s * 1024.0f);
        if (bk > NBUCK - 1) bk = NBUCK - 1;
        if (bk < 0) bk = 0;
        atomicAdd(&sh[bk], 1);
    }
    __syncthreads();
    for (int p = t; p < NBUCK; p += 256)
        if (sh[p]) atomicAdd(&g_hist[b][p], sh[p]);
}

// ---------------- kernel B: suffix-sum scan, find threshold bucket ----------------
__global__ void k_findthr() {
    __shared__ int s[NBUCK];
    int b = blockIdx.x, t = threadIdx.x;
    s[t] = g_hist[b][t];
    __syncthreads();
    for (int off = 1; off < NBUCK; off <<= 1) {
        int v = (t + off < NBUCK) ? s[t + off] : 0;
        __syncthreads();
        s[t] += v;
        __syncthreads();
    }
    if (s[t] >= KSEL && (t == NBUCK - 1 || s[t + 1] < KSEL))
        g_bstar[b] = t;
}

// ---------------- kernel C: compact candidates >= threshold bucket ----------------
// grid (256, NB) x 256 threads
__global__ void k_compact(const float2* __restrict__ scores) {
    int t = threadIdx.x;
    int b = blockIdx.y;
    int bstar = g_bstar[b];
    int base = blockIdx.x * 1024;
    const float2* sp = scores + (size_t)b * NN;
    #pragma unroll
    for (int r = 0; r < 4; ++r) {
        int i = base + r * 256 + t;
        float s = sp[i].y;
        int bk = (int)(s * 1024.0f);
        if (bk > NBUCK - 1) bk = NBUCK - 1;
        if (bk >= bstar) {
            int pos = atomicAdd(&g_cnt[b], 1);
            if (pos < CAP) {
                unsigned sb = __float_as_uint(s);   // s >= 0 -> monotonic bits
                g_keys[b][pos] =
                    ((unsigned long long)sb << 32) | (0xFFFFFFFFu - (unsigned)i);
            }
        }
    }
}

// ---------------- kernel D: bitonic sort (desc) of up to 8192 keys ----------------
__global__ void k_sort() {
    extern __shared__ unsigned long long sk[];
    int b = blockIdx.x, t = threadIdx.x;
    int n = g_cnt[b];
    if (n > CAP) n = CAP;
    for (int p = t; p < CAP; p += 1024)
        sk[p] = (p < n) ? g_keys[b][p] : 0ULL;
    __syncthreads();
    for (int k = 2; k <= CAP; k <<= 1) {
        for (int j = k >> 1; j > 0; j >>= 1) {
            for (int i = t; i < CAP; i += 1024) {
                int ixj = i ^ j;
                if (ixj > i) {
                    unsigned long long a = sk[i], c = sk[ixj];
                    bool desc = ((i & k) == 0);
                    if (desc ? (a < c) : (a > c)) { sk[i] = c; sk[ixj] = a; }
                }
            }
            __syncthreads();
        }
    }
    for (int r = t; r < KSEL; r += 1024)
        g_topidx[b][r] = (int)(0xFFFFFFFFu - (unsigned)(sk[r] & 0xFFFFFFFFull));
}

// ---------------- kernel E: gather + apply box deltas + clip ----------------
__global__ void k_boxes(const float4* __restrict__ deltas,
                        const float4* __restrict__ anchors) {
    int gid = blockIdx.x * blockDim.x + threadIdx.x;
    if (gid >= NB * KSEL) return;
    int b = gid / KSEL;
    int r = gid - b * KSEL;
    int j = g_topidx[b][r];
    float4 a = anchors[(size_t)b * NN + j];
    float4 d = deltas[(size_t)b * NN + j];
    float dx = d.x * 0.1f, dy = d.y * 0.1f, dw = d.z * 0.2f, dh = d.w * 0.2f;
    float w  = a.z - a.x;
    float h  = a.w - a.y;
    float cx = a.x + 0.5f * w;
    float cy = a.y + 0.5f * h;
    cx = cx + dx * w;
    cy = cy + dy * h;
    w  = w * expf(dw);
    h  = h * expf(dh);
    float x0 = cx - 0.5f * w, y0 = cy - 0.5f * h;
    float x1 = cx + 0.5f * w, y1 = cy + 0.5f * h;
    x0 = fminf(fmaxf(x0, 0.0f), 1.0f);
    y0 = fminf(fmaxf(y0, 0.0f), 1.0f);
    x1 = fminf(fmaxf(x1, 0.0f), 1.0f);
    y1 = fminf(fmaxf(y1, 0.0f), 1.0f);
    g_boxes[b][r] = make_float4(x0, y0, x1, y1);
}

// ---------------- kernel F: pairwise suppression bitmask ----------------
// grid (24, 94, NB) x 256 threads. Tile: 64 rows x 256 cols.
// Bit (i, j) set iff j > i and IoU(box_i, box_j) > 0.7 (bit-exact vs fdiv test).
__global__ void k_mask() {
    int b  = blockIdx.z;
    int ir = blockIdx.y * 64;
    int jc = blockIdx.x * 256;
    if (jc + 256 <= ir) return;     // all pairs have j < i strictly: never read
    __shared__ float4 srow[64];
    __shared__ float  sarea[64];
    int t = threadIdx.x;
    if (t < 64) {
        int i = ir + t;
        float4 bx = (i < KSEL) ? g_boxes[b][i] : make_float4(0.f, 0.f, 0.f, 0.f);
        srow[t]  = bx;
        sarea[t] = __fmul_rn(bx.z - bx.x, bx.w - bx.y);
    }
    int j = jc + t;
    float4 cb = (j < KSEL) ? g_boxes[b][j] : make_float4(0.f, 0.f, 0.f, 0.f);
    float  ca = __fmul_rn(cb.z - cb.x, cb.w - cb.y);
    __syncthreads();

    int lane = t & 31, warp = t >> 5;
    unsigned* mask32 = (unsigned*)&g_mask[b][0][0];
    int nrows = KSEL - ir; if (nrows > 64) nrows = 64;
    for (int r = 0; r < nrows; ++r) {
        int i = ir + r;
        float4 rb = srow[r];
        float  ra = sarea[r];
        bool p = false;
        if (j > i && j < KSEL) {
            float ltx = fmaxf(rb.x, cb.x);
            float lty = fmaxf(rb.y, cb.y);
            float rbx = fminf(rb.z, cb.z);
            float rby = fminf(rb.w, cb.w);
            float wx = fmaxf(rbx - ltx, 0.0f);
            float wy = fmaxf(rby - lty, 0.0f);
            float inter = __fmul_rn(wx, wy);
            // exact reference order: ((a_i + a_j) - inter) + 1e-12
            float denom = ((ra + ca) - inter) + 1e-12f;
            float lim = __fmul_rn(NMS_THR, denom);
            if      (inter > lim * 1.00001f) p = true;     // safely above
            else if (inter < lim * 0.99999f) p = false;    // safely below
            else    p = (__fdiv_rn(inter, denom) > NMS_THR);  // exact, rare
        }
        unsigned bal = __ballot_sync(0xFFFFFFFFu, p);
        if (lane == 0)
            mask32[(size_t)i * (2 * MROW64) + (jc >> 5) + warp] = bal;
    }
}

// ---------------- kernel G: serial greedy scan over bitmask, 1 warp/batch ------
__global__ void __launch_bounds__(32, 1) k_scan(float* __restrict__ out) {
    __shared__ int sidx[PROP];
    int b = blockIdx.x, lane = threadIdx.x;
    float4* outB = (float4*)(out + (size_t)b * PROP * 4);
    for (int p = lane; p < PROP; p += 32)
        outB[p] = make_float4(0.f, 0.f, 0.f, 0.f);

    unsigned long long r0 = 0, r1 = 0, r2 = 0;   // remv bits: words lane, lane+32, lane+64
    int kept = 0;
    for (int i = 0; i < KSEL; ++i) {
        // prefetch mask row i+16 into L1 (6 x 128B lines, one instruction)
        if (i + 16 < KSEL && lane < 6) {
            const char* pf = (const char*)&g_mask[b][i + 16][0] + lane * 128;
            asm volatile("prefetch.global.L1 [%0];" :: "l"(pf));
        }
        int w = i >> 6;
        int slot = w >> 5;                        // uniform across warp
        unsigned long long v = (slot == 0) ? r0 : ((slot == 1) ? r1 : r2);
        unsigned long long word = __shfl_sync(0xFFFFFFFFu, v, w & 31);
        if (!((word >> (i & 63)) & 1ULL)) {
            if (lane == 0) sidx[kept] = i;
            ++kept;
            if (kept >= PROP) break;
            const unsigned long long* row = &g_mask[b][i][0];
            r0 |= row[lane];
            r1 |= row[lane + 32];
            r2 |= row[lane + 64];
        }
    }
    __syncwarp();
    for (int p = lane; p < kept; p += 32)
        outB[p] = g_boxes[b][sidx[p]];
}

// ---------------- launch ----------------
extern "C" void kernel_launch(void* const* d_in, const int* in_sizes, int n_in,
                              void* d_out, int out_size) {
    const float2* scores  = (const float2*)d_in[0];  // (4,262144,2)
    const float4* deltas  = (const float4*)d_in[1];  // (4,262144,4)
    const float4* anchors = (const float4*)d_in[2];  // (4,262144,4)
    float* out = (float*)d_out;                      // (4,1000,4)

    cudaFuncSetAttribute(k_sort, cudaFuncAttributeMaxDynamicSharedMemorySize,
                         CAP * sizeof(unsigned long long));

    k_zero<<<8, 512>>>();
    k_hist<<<dim3(256, NB), 256>>>(scores);
    k_findthr<<<NB, NBUCK>>>();
    k_compact<<<dim3(256, NB), 256>>>(scores);
    k_sort<<<NB, 1024, CAP * sizeof(unsigned long long)>>>();
    k_boxes<<<(NB * KSEL + 255) / 256, 256>>>(deltas, anchors);
    k_mask<<<dim3(24, 94, NB), 256>>>();
    k_scan<<<NB, 32>>>(out);
}